// round 17
// baseline (speedup 1.0000x reference)
#include <cuda_runtime.h>
#include <cstdint>

#define NN    65536
#define EE    262144
#define EDIMC 300
#define HD    256
#define KCP   576
#define KC    556
#define N3H   768

// ---- scratch (device globals; allocation-free) ----
__device__ float g_ht [(size_t)NN * HD];    // segsum(prev_h), raw fp32
__device__ float g_fx [(size_t)NN * HD];
__device__ float g_fc [(size_t)NN * HD];
__device__ float g_big[(size_t)NN * N3H];
__device__ float g_WcT[(size_t)N3H * KCP];
__device__ float g_WfT[(size_t)HD * KCP];
__device__ float g_UfT[(size_t)HD * HD];
__device__ int   g_rowstart[NN + 1];

// ---------------------------------------------------------------------------
__device__ __forceinline__ float rna(float f) {
    uint32_t u;
    asm("cvt.rna.tf32.f32 %0, %1;" : "=r"(u) : "f"(f));
    return __uint_as_float(u);
}

// all three weight transposes + CSR rowstart in ONE wide kernel
#define WC_E (N3H * KCP)               // 442368
#define WF_E (HD * KCP)                // 147456
#define UF_E (HD * HD)                 // 65536
#define RS_E (NN + 1)                  // 65537
__global__ void k_trall(const float* __restrict__ Wc, const float* __restrict__ Wf,
                        const float* __restrict__ Uf, const int* __restrict__ seg) {
    int i = blockIdx.x * blockDim.x + threadIdx.x;
    if (i < WC_E) {
        int n = i / KCP, k = i % KCP;
        g_WcT[i] = (k < KC) ? rna(Wc[(size_t)k * N3H + n]) : 0.f;
    } else if (i < WC_E + WF_E) {
        int j = i - WC_E;
        int n = j / KCP, k = j % KCP;
        g_WfT[j] = (k < EDIMC) ? rna(Wf[(size_t)k * HD + n]) : 0.f;
    } else if (i < WC_E + WF_E + UF_E) {
        int j = i - WC_E - WF_E;
        int n = j / HD, k = j % HD;
        g_UfT[j] = rna(Uf[(size_t)k * HD + n]);
    } else if (i < WC_E + WF_E + UF_E + RS_E) {
        int j = i - WC_E - WF_E - UF_E;
        int lo = 0, hi = EE;
        while (lo < hi) {
            int m = (lo + hi) >> 1;
            if (seg[m] < j) lo = m + 1; else hi = m;
        }
        g_rowstart[j] = lo;
    }
}

// segsum only: g_ht[j][d] = sum over children of prev_h (raw fp32)
__global__ void k_pack(const float* __restrict__ prev_h) {
    int j = blockIdx.x, d = threadIdx.x;    // blockDim = 256
    int s = g_rowstart[j], e = g_rowstart[j + 1];
    float acc = 0.f;
    for (int k = s; k < e; k++) acc += prev_h[(size_t)k * HD + d];
    g_ht[(size_t)j * HD + d] = acc;
}

__device__ __forceinline__ float sigm_f(float x) { return 1.f / (1.f + __expf(-x)); }
__device__ __forceinline__ float tanh_f(float x) { return 1.f - 2.f / (__expf(2.f * x) + 1.f); }

__global__ void k_final(float* __restrict__ out) {
    int j = blockIdx.x, d = threadIdx.x;
    size_t b = (size_t)j * N3H;
    float zi = g_big[b + d];
    float zo = g_big[b + HD + d];
    float zu = g_big[b + 2 * HD + d];
    float c = sigm_f(zi) * tanh_f(zu) + g_fc[(size_t)j * HD + d];
    float h = sigm_f(zo) * tanh_f(c);
    out[(size_t)j * HD + d] = c;
    out[(size_t)NN * HD + (size_t)j * HD + d] = h;
}

// ---------------------------------------------------------------------------
// common GEMM helpers
// ---------------------------------------------------------------------------
__device__ __forceinline__ uint32_t s2u(const void* p) {
    uint32_t a;
    asm("{ .reg .u64 t; cvta.to.shared.u64 t, %1; cvt.u32.u64 %0, t; }" : "=r"(a) : "l"(p));
    return a;
}
__device__ __forceinline__ void cpa16(uint32_t s, const void* g) {
    asm volatile("cp.async.cg.shared.global [%0], [%1], 16;" :: "r"(s), "l"(g));
}
// src-size variant: sz=0 -> zero-fill 16 bytes
__device__ __forceinline__ void cpa16z(uint32_t s, const void* g, int sz) {
    asm volatile("cp.async.cg.shared.global [%0], [%1], 16, %2;"
                 :: "r"(s), "l"(g), "r"(sz));
}
__device__ __forceinline__ void ldsm4(uint32_t* r, uint32_t addr) {
    asm volatile("ldmatrix.sync.aligned.m8n8.x4.shared.b16 {%0,%1,%2,%3}, [%4];"
                 : "=r"(r[0]), "=r"(r[1]), "=r"(r[2]), "=r"(r[3]) : "r"(addr));
}
#define MMA_TF32(d, a, b)                                                      \
    asm volatile("mma.sync.aligned.m16n8k8.row.col.f32.tf32.tf32.f32 "         \
                 "{%0,%1,%2,%3}, {%4,%5,%6,%7}, {%8,%9}, {%0,%1,%2,%3};"       \
                 : "+f"(d[0]), "+f"(d[1]), "+f"(d[2]), "+f"(d[3])              \
                 : "r"(a[0]), "r"(a[1]), "r"(a[2]), "r"(a[3]),                 \
                   "r"(b[0]), "r"(b[1]))

__device__ __forceinline__ uint32_t sw128(int row, int cByte) {
    uint32_t off = row * 128 + cByte;
    return off ^ ((off >> 3) & 0x70);
}

// ---------------------------------------------------------------------------
// k_gemm128: CTA 128x128, 8 warps (4m x 2n), warp 32x64, 3-stage cp.async,
// one __syncthreads per iteration, 2 CTAs/SM.
// A is the VIRTUAL concat [x | h_tilde | 0]: chunks sourced per-k from
// x (k<300), g_ht (300<=k<556), zero-fill (k>=556).  Raw fp32 -> HW RZ tf32.
// Grid: blockIdx.x = N tile (fast), blockIdx.y = M tile.
// ---------------------------------------------------------------------------
#define STG128 32768                   // A 16KB + B 16KB
#define SMEM128 (3 * STG128)           // 96KB -> 2 CTAs/SM

__global__ __launch_bounds__(256, 2)
void k_gemm128(const float* __restrict__ Ax, const float* __restrict__ Ah,
               const float* __restrict__ B,
               float* __restrict__ C, const float* __restrict__ bias,
               int nk, int ldc) {
    extern __shared__ float sm[];
    const uint32_t sb = s2u(sm);
    const int tid = threadIdx.x;
    const int lane = tid & 31, wid = tid >> 5;
    const int warp_m = wid & 3;
    const int warp_n = wid >> 2;
    const int qid = lane >> 2, t4 = lane & 3;
    const int bm0 = blockIdx.y * 128, bn0 = blockIdx.x * 128;

    float acc[2][8][4];
#pragma unroll
    for (int mi = 0; mi < 2; mi++)
#pragma unroll
        for (int ni = 0; ni < 8; ni++)
#pragma unroll
            for (int r = 0; r < 4; r++) acc[mi][ni][r] = 0.f;

    const int lrow = lane & 15;
    const int lchu = (lane >> 4) * 16;

    auto loads = [&](int kt, int st) {
        const int k0 = kt << 5;
        const uint32_t aB = sb + st * STG128;
        const uint32_t bB = aB + 16384;
#pragma unroll
        for (int i = 0; i < 4; i++) {
            int idx = tid + i * 256;
            int row = idx >> 3, c = idx & 7;
            int gk = k0 + c * 4;
            // A chunk source select (gk uniform per thread across i: c=tid&7)
            const float* src;
            int sz = 16;
            if (gk < EDIMC)      src = Ax + (size_t)(bm0 + row) * EDIMC + gk;
            else if (gk < KC)    src = Ah + (size_t)(bm0 + row) * HD + (gk - EDIMC);
            else               { src = Ax; sz = 0; }
            cpa16z(aB + sw128(row, c * 16), src, sz);
            cpa16(bB + sw128(row, c * 16), B + (size_t)(bn0 + row) * KCP + gk);
        }
        asm volatile("cp.async.commit_group;" ::: "memory");
    };

    loads(0, 0);
    if (nk > 1) loads(1, 1);

    for (int kt = 0; kt < nk; kt++) {
        const int st = kt % 3;
        if (kt + 1 < nk)
            asm volatile("cp.async.wait_group 1;" ::: "memory");
        else
            asm volatile("cp.async.wait_group 0;" ::: "memory");
        __syncthreads();
        if (kt + 2 < nk) loads(kt + 2, (kt + 2) % 3);

        const uint32_t aB = sb + st * STG128;
        const uint32_t bB = aB + 16384;
#pragma unroll
        for (int kk = 0; kk < 32; kk += 8) {
            uint32_t af[2][4];
#pragma unroll
            for (int mi = 0; mi < 2; mi++) {
                int r = warp_m * 32 + mi * 16 + lrow;
                ldsm4(af[mi], aB + sw128(r, kk * 4 + lchu));
            }
            uint32_t bfr[8][2];
#pragma unroll
            for (int nb = 0; nb < 4; nb++) {
                uint32_t tmp[4];
                int r = warp_n * 64 + nb * 16 + lrow;
                ldsm4(tmp, bB + sw128(r, kk * 4 + lchu));
                bfr[2 * nb][0] = tmp[0]; bfr[2 * nb + 1][0] = tmp[1];
                bfr[2 * nb][1] = tmp[2]; bfr[2 * nb + 1][1] = tmp[3];
            }
#pragma unroll
            for (int mi = 0; mi < 2; mi++)
#pragma unroll
                for (int ni = 0; ni < 8; ni++)
                    MMA_TF32(acc[mi][ni], af[mi], bfr[ni]);
        }
    }

#pragma unroll
    for (int mi = 0; mi < 2; mi++) {
        int row = bm0 + warp_m * 32 + mi * 16 + qid;
#pragma unroll
        for (int ni = 0; ni < 8; ni++) {
            int col = bn0 + warp_n * 64 + ni * 8 + t4 * 2;
            float b0 = bias[col], b1 = bias[col + 1];
            float* p0 = &C[(size_t)row * ldc + col];
            p0[0] = acc[mi][ni][0] + b0;
            p0[1] = acc[mi][ni][1] + b1;
            float* p1 = &C[(size_t)(row + 8) * ldc + col];
            p1[0] = acc[mi][ni][2] + b0;
            p1[1] = acc[mi][ni][3] + b1;
        }
    }
}

// ---------------------------------------------------------------------------
// k_gemm64e: CTA 128x64, warp 32x32, 3 CTAs/SM, fused edge epilogue with
// staged prev_c + CTA-local segmented reduction (R16, measured good).
// ---------------------------------------------------------------------------
#define A64_B 16384
#define B64_B 8192
#define STG64 (A64_B + B64_B)          // 24KB
#define SMEM64 (3 * STG64)             // 72KB -> 3 CTAs/SM
#define RED_LD 68

__global__ __launch_bounds__(256, 3)
void k_gemm64e(const float* __restrict__ A, const float* __restrict__ B,
               int ld, int nk,
               const int* __restrict__ seg, const float* __restrict__ prevc,
               const float* __restrict__ fxp, float* __restrict__ fc) {
    extern __shared__ float sm[];
    const uint32_t sb = s2u(sm);
    const int tid = threadIdx.x;
    const int lane = tid & 31, wid = tid >> 5;
    const int warp_m = wid & 3;
    const int warp_n = wid >> 2;
    const int qid = lane >> 2, t4 = lane & 3;
    const int bm0 = blockIdx.y * 128, bn0 = blockIdx.x * 64;

    float acc[2][4][4];
#pragma unroll
    for (int mi = 0; mi < 2; mi++)
#pragma unroll
        for (int ni = 0; ni < 4; ni++)
#pragma unroll
            for (int r = 0; r < 4; r++) acc[mi][ni][r] = 0.f;

    const int lrow = lane & 15;
    const int lchu = (lane >> 4) * 16;

    auto loads = [&](int kt, int st) {
        const int k0 = kt << 5;
        const uint32_t aB = sb + st * STG64;
        const uint32_t bB = aB + A64_B;
#pragma unroll
        for (int i = 0; i < 4; i++) {
            int idx = tid + i * 256;
            int row = idx >> 3, c = idx & 7;
            cpa16(aB + sw128(row, c * 16), A + (size_t)(bm0 + row) * ld + k0 + c * 4);
        }
#pragma unroll
        for (int i = 0; i < 2; i++) {
            int idx = tid + i * 256;
            int row = idx >> 3, c = idx & 7;
            cpa16(bB + sw128(row, c * 16), B + (size_t)(bn0 + row) * ld + k0 + c * 4);
        }
        asm volatile("cp.async.commit_group;" ::: "memory");
    };

    loads(0, 0);
    if (nk > 1) loads(1, 1);

    for (int kt = 0; kt < nk; kt++) {
        const int st = kt % 3;
        if (kt + 1 < nk)
            asm volatile("cp.async.wait_group 1;" ::: "memory");
        else
            asm volatile("cp.async.wait_group 0;" ::: "memory");
        __syncthreads();
        if (kt + 2 < nk) loads(kt + 2, (kt + 2) % 3);

        const uint32_t aB = sb + st * STG64;
        const uint32_t bB = aB + A64_B;
#pragma unroll
        for (int kk = 0; kk < 32; kk += 8) {
            uint32_t af[2][4];
#pragma unroll
            for (int mi = 0; mi < 2; mi++) {
                int r = warp_m * 32 + mi * 16 + lrow;
                ldsm4(af[mi], aB + sw128(r, kk * 4 + lchu));
            }
            uint32_t bfr[4][2];
#pragma unroll
            for (int nb = 0; nb < 2; nb++) {
                uint32_t tmp[4];
                int r = warp_n * 32 + nb * 16 + lrow;
                ldsm4(tmp, bB + sw128(r, kk * 4 + lchu));
                bfr[2 * nb][0] = tmp[0]; bfr[2 * nb + 1][0] = tmp[1];
                bfr[2 * nb][1] = tmp[2]; bfr[2 * nb + 1][1] = tmp[3];
            }
#pragma unroll
            for (int mi = 0; mi < 2; mi++)
#pragma unroll
                for (int ni = 0; ni < 4; ni++)
                    MMA_TF32(acc[mi][ni], af[mi], bfr[ni]);
        }
    }

    // ---- fused edge epilogue: staged prev_c + segmented reduction ----
    __syncthreads();
    float* red = sm;                               // 128 x RED_LD
    float* pcS = sm + 128 * RED_LD;                // 128 x RED_LD
    int*   sseg = (int*)(sm + 2 * 128 * RED_LD);   // 128 ints
    if (tid < 128) sseg[tid] = seg[bm0 + tid];

#pragma unroll
    for (int i = 0; i < 8; i++) {
        int idx = tid + i * 256;
        int row = idx >> 4, q = idx & 15;
        float4 v = *(const float4*)(prevc + (size_t)(bm0 + row) * HD + bn0 + q * 4);
        *(float4*)(pcS + row * RED_LD + q * 4) = v;
    }
    __syncthreads();

#pragma unroll
    for (int mi = 0; mi < 2; mi++) {
        int lr0 = warp_m * 32 + mi * 16 + qid;
        int lr1 = lr0 + 8;
        int j0 = sseg[lr0], j1 = sseg[lr1];
#pragma unroll
        for (int ni = 0; ni < 4; ni++) {
            int lc = warp_n * 32 + ni * 8 + t4 * 2;
            int col = bn0 + lc;
            const float* f0p = fxp + (size_t)j0 * HD + col;
            const float* f1p = fxp + (size_t)j1 * HD + col;
            float2 pc0 = *(const float2*)(pcS + lr0 * RED_LD + lc);
            float2 pc1 = *(const float2*)(pcS + lr1 * RED_LD + lc);
            red[lr0 * RED_LD + lc]     = sigm_f(acc[mi][ni][0] + f0p[0]) * pc0.x;
            red[lr0 * RED_LD + lc + 1] = sigm_f(acc[mi][ni][1] + f0p[1]) * pc0.y;
            red[lr1 * RED_LD + lc]     = sigm_f(acc[mi][ni][2] + f1p[0]) * pc1.x;
            red[lr1 * RED_LD + lc + 1] = sigm_f(acc[mi][ni][3] + f1p[1]) * pc1.y;
        }
    }
    __syncthreads();

    const int c  = tid & 63;
    const int rh = (tid >> 6) * 32;
    const int col = bn0 + c;
    float s = 0.f;
    int cur = sseg[rh];
    for (int r = 0; r < 32; r++) {
        int jj = sseg[rh + r];
        if (jj != cur) {
            atomicAdd(&fc[(size_t)cur * HD + col], s);
            s = 0.f; cur = jj;
        }
        s += red[(rh + r) * RED_LD + c];
    }
    atomicAdd(&fc[(size_t)cur * HD + col], s);
}

// ---------------------------------------------------------------------------
extern "C" void kernel_launch(void* const* d_in, const int* in_sizes, int n_in,
                              void* d_out, int out_size) {
    const float* x      = (const float*)d_in[0];
    const float* prev_c = (const float*)d_in[1];
    const float* prev_h = (const float*)d_in[2];
    const float* Wc     = (const float*)d_in[3];
    const float* bc     = (const float*)d_in[4];
    const float* Wf     = (const float*)d_in[5];
    const float* Uf     = (const float*)d_in[6];
    const float* bf     = (const float*)d_in[7];
    const int*   seg    = (const int*)d_in[8];
    float* out = (float*)d_out;

    float *p_ht, *p_fx, *p_fc, *p_big, *p_WcT, *p_WfT, *p_UfT;
    cudaGetSymbolAddress((void**)&p_ht,  g_ht);
    cudaGetSymbolAddress((void**)&p_fx,  g_fx);
    cudaGetSymbolAddress((void**)&p_fc,  g_fc);
    cudaGetSymbolAddress((void**)&p_big, g_big);
    cudaGetSymbolAddress((void**)&p_WcT, g_WcT);
    cudaGetSymbolAddress((void**)&p_WfT, g_WfT);
    cudaGetSymbolAddress((void**)&p_UfT, g_UfT);

    cudaFuncSetAttribute(k_gemm128, cudaFuncAttributeMaxDynamicSharedMemorySize, SMEM128);
    cudaFuncSetAttribute(k_gemm64e, cudaFuncAttributeMaxDynamicSharedMemorySize, SMEM64);

    // kernel order (memset not counted by ncu): trall0, pack1, fx2, hU3<-profiled
    k_trall<<<(WC_E + WF_E + UF_E + RS_E + 255) / 256, 256>>>(Wc, Wf, Uf, seg); // 0
    k_pack<<<NN, 256>>>(prev_h);                                                // 1
    cudaMemsetAsync(p_fc, 0, (size_t)NN * HD * sizeof(float));

    // fx = x @ Wf + bf      N=256, K=320 (chunks past 300 hit zero weights)
    dim3 gfx(HD / 128, NN / 128);                                               // 2
    k_gemm128<<<gfx, 256, SMEM128>>>(x, p_ht, p_WfT, p_fx, bf, 10, HD);

    // hU GEMM + fused edge epilogue (A = raw prev_h, HW tf32 truncation)
    dim3 ghu(HD / 64, EE / 128);                                                // 3
    k_gemm64e<<<ghu, 256, SMEM64>>>(prev_h, p_UfT, HD, 8,
                                    seg, prev_c, p_fx, p_fc);

    // big = [x|h_tilde] @ Wc + bc      N=768, K=576 (zero-fill tail)
    dim3 gbig(N3H / 128, NN / 128);                                             // 4
    k_gemm128<<<gbig, 256, SMEM128>>>(x, p_ht, p_WcT, p_big, bc, 18, N3H);

    k_final<<<NN, 256>>>(out);                                                  // 5
}